// round 16
// baseline (speedup 1.0000x reference)
#include <cuda_runtime.h>
#include <cuda_fp16.h>
#include <cstdint>
#include <math.h>

#define H      1024
#define L      512
#define G4     4096
#define KIN    4096
#define FIVEH  5120
#define LABELS 122
#define NBLK   128
#define NTHR   512

// ---- static device scratch ----
__device__ float g_Wrec[G4 * H];                 // 16 MB
__device__ float g_bias[G4];
__device__ float g_P[L * G4];                    // 8 MB
__device__ float g_outs[L * H];                  // 2 MB
__device__ int   g_pub[2][NBLK][32];             // publish lines: 8 h-words + flag@[8], 128B each
__device__ __half g_W_h[G4 * KIN];               // 32 MB  (fp16 truncation of W_ih[:, :4096])
__device__ __half g_F_h[L * KIN];                // 4 MB   (fp16 truncation of feats)

// ============ PTX helpers (plain sm_80+ features only) ============
__device__ __forceinline__ uint32_t smem_u32(const void* p) {
    uint32_t a;
    asm("{ .reg .u64 t; cvta.to.shared.u64 t, %1; cvt.u32.u64 %0, t; }" : "=r"(a) : "l"(p));
    return a;
}
#define CP_ASYNC16(dst, src) \
    asm volatile("cp.async.cg.shared.global [%0], [%1], 16;" :: "r"(dst), "l"(src))
#define CP_COMMIT() asm volatile("cp.async.commit_group;" ::: "memory")
#define CP_WAIT(n)  asm volatile("cp.async.wait_group %0;" :: "n"(n) : "memory")

__device__ __forceinline__ void ldm_x4(uint32_t& d0, uint32_t& d1, uint32_t& d2, uint32_t& d3,
                                       uint32_t addr) {
    asm volatile("ldmatrix.sync.aligned.m8n8.x4.shared.b16 {%0,%1,%2,%3}, [%4];"
                 : "=r"(d0), "=r"(d1), "=r"(d2), "=r"(d3) : "r"(addr));
}
__device__ __forceinline__ void mma_f16(float* c, const uint32_t* a, const uint32_t* b) {
    asm volatile("mma.sync.aligned.m16n8k16.row.col.f32.f16.f16.f32 "
                 "{%0,%1,%2,%3}, {%4,%5,%6,%7}, {%8,%9}, {%0,%1,%2,%3};"
                 : "+f"(c[0]), "+f"(c[1]), "+f"(c[2]), "+f"(c[3])
                 : "r"(a[0]), "r"(a[1]), "r"(a[2]), "r"(a[3]), "r"(b[0]), "r"(b[1]));
}
__device__ __forceinline__ void fma2(float2& d, const float2& a, const float2& b) {
    unsigned long long dd = *reinterpret_cast<const unsigned long long*>(&d);
    unsigned long long aa = *reinterpret_cast<const unsigned long long*>(&a);
    unsigned long long bb = *reinterpret_cast<const unsigned long long*>(&b);
    asm("fma.rn.f32x2 %0, %1, %2, %0;" : "+l"(dd) : "l"(aa), "l"(bb));
    d = *reinterpret_cast<float2*>(&dd);
}
__device__ __forceinline__ float sigm_f(float x) {
    return __fdividef(1.f, 1.f + __expf(-x));
}
__device__ __forceinline__ float tanh_f(float x) {
    return __fdividef(2.f, 1.f + __expf(-2.f * x)) - 1.f;
}

// ============================================================
// Kernel 1a: W_rec = W_ih[:,4096:] + W_hh, bias, pub flags
// ============================================================
__global__ void prep_kernel(const float* __restrict__ W_ih, const float* __restrict__ W_hh,
                            const float* __restrict__ b_ih, const float* __restrict__ b_hh) {
    int idx = blockIdx.x * blockDim.x + threadIdx.x;
    if (idx < G4 * H) {
        int r = idx >> 10, j = idx & 1023;
        g_Wrec[idx] = W_ih[(size_t)r * FIVEH + KIN + j] + W_hh[idx];
    }
    if (idx < G4) g_bias[idx] = b_ih[idx] + b_hh[idx];
    if (idx < 2 * NBLK * 32) (&g_pub[0][0][0])[idx] = 0;
}

// Kernel 1b: W_ih[:, :4096] -> fp16
__global__ void conv_w_kernel(const float* __restrict__ W_ih) {
    int idx = blockIdx.x * blockDim.x + threadIdx.x;     // 16.7M
    int r = idx >> 12, c = idx & 4095;
    g_W_h[idx] = __float2half_rn(W_ih[(size_t)r * FIVEH + c]);
}

// Kernel 1c: feats = concat(x, hi) -> fp16
__global__ void conv_f_kernel(const float* __restrict__ x, const float* __restrict__ hi) {
    int idx = blockIdx.x * blockDim.x + threadIdx.x;     // 2M
    int r = idx >> 12, c = idx & 4095;
    float v = (c < 2048) ? x[(size_t)r * 2048 + c] : hi[(size_t)r * 2048 + (c - 2048)];
    g_F_h[idx] = __float2half_rn(v);
}

// ============================================================
// Kernel 2: fp16 HMMA GEMM, 1-product (F_h * W_h).
// Work = 1/3 of the original bf16 3-product (throughput-ceiling
// model: dur proportional to product count — validated R15).
// 4-stage cp.async pipeline (compute/kt halved -> latency cover needed).
// ============================================================
#define BK       32
#define KTILES   (KIN / BK)          // 128
#define LDS_B    80                  // padded row stride in bytes (40 fp16)
#define T_AH     0                   // 128 rows * 80B = 10240
#define T_BH     10240
#define STAGE_B  20480
#define NSTAGE   4
#define GSMEM    (NSTAGE * STAGE_B)  // 81920

__global__ __launch_bounds__(256, 1)
void gemm_hmma(float* __restrict__ dummy) {
    extern __shared__ char smem[];
    uint32_t sb = smem_u32(smem);
    int tid = threadIdx.x, lane = tid & 31, wid = tid >> 5;
    int warp_m = wid >> 2, warp_n = wid & 3;     // 2 x 4 warps
    int bn = blockIdx.x, bm = blockIdx.y;        // 32 x 4

    // ---- cp.async mapping: 1024 16B-chunks/stage = 4/thread ----
    const char* gsrc[4];
    uint32_t    sdst[4];
#pragma unroll
    for (int j = 0; j < 4; j++) {
        int c = j * 256 + tid;
        int tile = c >> 9, cc = c & 511, row = cc >> 2, seg = cc & 3;
        const __half* base = tile ? g_W_h : g_F_h;
        int grow = (tile ? bn : bm) * 128 + row;
        gsrc[j] = (const char*)(base + (size_t)grow * KIN + seg * 8);
        sdst[j] = sb + tile * 10240 + row * LDS_B + seg * 16;
    }

    int r8 = lane & 7, mi01 = (lane >> 3) & 1, kh = (lane >> 4) & 1;
    uint32_t aoff = (uint32_t)((warp_m * 64 + mi01 * 8 + r8) * LDS_B + kh * 16);
    uint32_t boff = (uint32_t)((warp_n * 32 + mi01 * 8 + r8) * LDS_B + kh * 16);

    float acc[4][4][4];
#pragma unroll
    for (int i = 0; i < 4; i++)
#pragma unroll
        for (int j = 0; j < 4; j++)
#pragma unroll
            for (int q = 0; q < 4; q++) acc[i][j][q] = 0.f;

    // prologue: stages 0..2
#pragma unroll
    for (int s = 0; s < NSTAGE - 1; s++) {
#pragma unroll
        for (int j = 0; j < 4; j++)
            CP_ASYNC16(sdst[j] + s * STAGE_B, gsrc[j] + (size_t)s * BK * 2);
        CP_COMMIT();
    }

    for (int kt = 0; kt < KTILES; kt++) {
        int kp = kt + NSTAGE - 1;
        if (kp < KTILES) {
            uint32_t stoff = (kp & (NSTAGE - 1)) * STAGE_B;
            size_t goff = (size_t)kp * BK * 2;
#pragma unroll
            for (int j = 0; j < 4; j++) CP_ASYNC16(sdst[j] + stoff, gsrc[j] + goff);
        }
        CP_COMMIT();                 // possibly empty — uniform group accounting
        CP_WAIT(NSTAGE - 1);
        __syncthreads();

        uint32_t st = sb + (kt & (NSTAGE - 1)) * STAGE_B;
#pragma unroll
        for (int ks = 0; ks < 2; ks++) {
            uint32_t ko = ks * 32;
            uint32_t ah[4][4], bh[4][2];
#pragma unroll
            for (int mt = 0; mt < 4; mt++) {
                uint32_t a = aoff + mt * (16 * LDS_B) + ko;
                ldm_x4(ah[mt][0], ah[mt][1], ah[mt][2], ah[mt][3], st + T_AH + a);
            }
#pragma unroll
            for (int g = 0; g < 2; g++) {
                uint32_t b = boff + g * (16 * LDS_B) + ko;
                uint32_t d0, d1, d2, d3;
                ldm_x4(d0, d1, d2, d3, st + T_BH + b);
                bh[g * 2][0] = d0; bh[g * 2][1] = d2;
                bh[g * 2 + 1][0] = d1; bh[g * 2 + 1][1] = d3;
            }
#pragma unroll
            for (int mt = 0; mt < 4; mt++)
#pragma unroll
                for (int nt = 0; nt < 4; nt++)
                    mma_f16(acc[mt][nt], ah[mt], bh[nt]);
        }
        __syncthreads();
    }

    int gid = lane >> 2, tig = lane & 3;
#pragma unroll
    for (int mt = 0; mt < 4; mt++) {
        int row0 = bm * 128 + warp_m * 64 + mt * 16 + gid;
#pragma unroll
        for (int nt = 0; nt < 4; nt++) {
            int col = bn * 128 + warp_n * 32 + nt * 8 + tig * 2;
            float2 bias2 = *(const float2*)&g_bias[col];
            float2 v0 = make_float2(acc[mt][nt][0] + bias2.x, acc[mt][nt][1] + bias2.y);
            float2 v1 = make_float2(acc[mt][nt][2] + bias2.x, acc[mt][nt][3] + bias2.y);
            *(float2*)&g_P[(size_t)row0 * G4 + col] = v0;
            *(float2*)&g_P[(size_t)(row0 + 8) * G4 + col] = v1;
        }
    }
    if (dummy) *dummy = 0.f;
}

// ============================================================
// Kernel 3: persistent LSTM recurrence — R11 scheme with ONE change:
// after relaxed-poll detect, use a local fence.acq_rel.gpu instead of
// an acquire RE-LOAD of the flag (removes one L2 RTT ~250-380 cyc
// from the per-step critical path; writer's st.release pairs with it).
// ============================================================
__global__ __launch_bounds__(NTHR, 1) void lstm_kernel() {
    __shared__ float h_sh[H];
    __shared__ float red[32][4];

    int tid = threadIdx.x, b = blockIdx.x;
    int w = tid >> 5, l = tid & 31;
    int rg = w >> 1;                  // row group 0..7 (4 rows each)
    int cc = w & 1;                   // col chunk 0..1 (512 cols each)
    int jbase = b * 8;

    float2 wreg[4][8];
#pragma unroll
    for (int row = 0; row < 4; row++) {
        int rr = rg * 4 + row;
        int r = (rr >> 3) * 1024 + jbase + (rr & 7);
        const float2* wp = (const float2*)(g_Wrec + (size_t)r * H) + cc * 256;
#pragma unroll
        for (int i = 0; i < 8; i++) wreg[row][i] = wp[i * 32 + l];
    }
    h_sh[tid] = 0.f; h_sh[tid + 512] = 0.f;
    float c_reg = 0.f;
    int prow = (l >> 3) * 1024 + jbase + (l & 7);   // used by warp 15
    float pval = 0.f, pval_next = 0.f;
    if (w == 15) pval = __ldcg(&g_P[prow]);
    __syncthreads();

    for (int t = 0; t < L; t++) {
        if (w == 15 && t + 1 < L) pval_next = __ldcg(&g_P[(size_t)(t + 1) * G4 + prow]);

        // ---- phase A: matvec slice (4 rows x 16 cols per thread) ----
        float2 acc[4];
#pragma unroll
        for (int row = 0; row < 4; row++) acc[row] = make_float2(0.f, 0.f);
        const float2* h2 = (const float2*)h_sh;
#pragma unroll
        for (int i = 0; i < 8; i++) {
            float2 hv = h2[cc * 256 + i * 32 + l];
#pragma unroll
            for (int row = 0; row < 4; row++) fma2(acc[row], wreg[row][i], hv);
        }
        float a0 = acc[0].x + acc[0].y, a1 = acc[1].x + acc[1].y;
        float a2 = acc[2].x + acc[2].y, a3 = acc[3].x + acc[3].y;
        a0 += __shfl_xor_sync(0xffffffffu, a0, 16);
        a1 += __shfl_xor_sync(0xffffffffu, a1, 16);
        a2 += __shfl_xor_sync(0xffffffffu, a2, 16);
        a3 += __shfl_xor_sync(0xffffffffu, a3, 16);
        float v0 = (l & 16) ? a2 : a0;
        float v1 = (l & 16) ? a3 : a1;
        v0 += __shfl_xor_sync(0xffffffffu, v0, 8);
        v1 += __shfl_xor_sync(0xffffffffu, v1, 8);
        float u = (l & 8) ? v1 : v0;
        u += __shfl_xor_sync(0xffffffffu, u, 4);
        u += __shfl_xor_sync(0xffffffffu, u, 2);
        u += __shfl_xor_sync(0xffffffffu, u, 1);
        if ((l & 7) == 0) red[rg * 4 + (l >> 3)][cc] = u;
        __syncthreads();                         // BAR1

        // ---- phase B: gates+publish (warp 15) | poll (warps 11-14) ----
        if (w == 15) {
            float gate = pval + red[l][0] + red[l][1];
            pval = pval_next;
            float fg = __shfl_sync(0xffffffffu, gate, l + 8);
            float gg = __shfl_sync(0xffffffffu, gate, l + 16);
            float og = __shfl_sync(0xffffffffu, gate, l + 24);
            if (l < 8) {
                float cn = sigm_f(fg) * c_reg + sigm_f(gate) * tanh_f(gg);
                float hn = sigm_f(og) * tanh_f(cn);
                c_reg = cn;
                h_sh[jbase + l] = hn;                              // own slice -> smem
                g_outs[(size_t)t * H + jbase + l] = hn;            // for FC
                if (t < L - 1) g_pub[t & 1][b][l] = __float_as_int(hn);
            }
            __syncwarp(0xffffffffu);
            if (l == 0 && t < L - 1) {
                asm volatile("st.release.gpu.global.s32 [%0], %1;"
                             :: "l"(&g_pub[t & 1][b][8]), "r"(t + 1) : "memory");
            }
        } else if (w >= 11 && t < L - 1) {
            int ptid = tid - 352;                 // 0..127
            if (ptid != b) {
                const int* line = &g_pub[t & 1][ptid][0];
                int v, tries = 0;
                for (;;) {
                    asm volatile("ld.relaxed.gpu.global.s32 %0, [%1];"
                                 : "=r"(v) : "l"(line + 8) : "memory");
                    if (v >= t + 1) break;
                    if (++tries > 2) asm volatile("nanosleep.u32 40;");
                }
                asm volatile("fence.acq_rel.gpu;" ::: "memory");   // acquire upgrade, no L2 RTT
                int d0, d1, d2, d3, d4, d5, d6, d7;
                asm volatile("ld.global.cg.v4.s32 {%0,%1,%2,%3}, [%4];"
                             : "=r"(d0), "=r"(d1), "=r"(d2), "=r"(d3) : "l"(line) : "memory");
                asm volatile("ld.global.cg.v4.s32 {%0,%1,%2,%3}, [%4];"
                             : "=r"(d4), "=r"(d5), "=r"(d6), "=r"(d7) : "l"(line + 4) : "memory");
                int hb = ptid * 8;
                h_sh[hb + 0] = __int_as_float(d0); h_sh[hb + 1] = __int_as_float(d1);
                h_sh[hb + 2] = __int_as_float(d2); h_sh[hb + 3] = __int_as_float(d3);
                h_sh[hb + 4] = __int_as_float(d4); h_sh[hb + 5] = __int_as_float(d5);
                h_sh[hb + 6] = __int_as_float(d6); h_sh[hb + 7] = __int_as_float(d7);
            }
        }
        __syncthreads();                         // BAR2
    }
}

// ============================================================
// Kernel 4: FC — 8 timesteps per block for W_fc reuse
// ============================================================
__global__ __launch_bounds__(256) void fc_kernel(const float* __restrict__ W_fc,
                                                 const float* __restrict__ b_fc,
                                                 float* __restrict__ out) {
    int t0 = blockIdx.x * 8;
    __shared__ float hsh[8][H];
    for (int i = threadIdx.x; i < 8 * H; i += 256)
        hsh[i >> 10][i & 1023] = g_outs[(size_t)t0 * H + i];
    __syncthreads();
    int w = threadIdx.x >> 5, l = threadIdx.x & 31;
    for (int lab = w; lab < LABELS; lab += 8) {
        const float* wr = W_fc + (size_t)lab * H;
        float wv[32];
#pragma unroll
        for (int i = 0; i < 32; i++) wv[i] = wr[l + 32 * i];
        float s[8];
#pragma unroll
        for (int tt = 0; tt < 8; tt++) s[tt] = 0.f;
#pragma unroll
        for (int i = 0; i < 32; i++)
#pragma unroll
            for (int tt = 0; tt < 8; tt++) s[tt] += wv[i] * hsh[tt][l + 32 * i];
#pragma unroll
        for (int off = 16; off; off >>= 1)
#pragma unroll
            for (int tt = 0; tt < 8; tt++) s[tt] += __shfl_xor_sync(0xffffffffu, s[tt], off);
        if (l == 0) {
#pragma unroll
            for (int tt = 0; tt < 8; tt++)
                out[(size_t)(t0 + tt) * LABELS + lab] = s[tt] + b_fc[lab];
        }
    }
}

// ============================================================
extern "C" void kernel_launch(void* const* d_in, const int* in_sizes, int n_in,
                              void* d_out, int out_size) {
    const float* x    = (const float*)d_in[0];
    const float* hi   = (const float*)d_in[1];
    const float* W_ih = (const float*)d_in[2];
    const float* W_hh = (const float*)d_in[3];
    const float* b_ih = (const float*)d_in[4];
    const float* b_hh = (const float*)d_in[5];
    const float* W_fc = (const float*)d_in[6];
    const float* b_fc = (const float*)d_in[7];
    float* out = (float*)d_out;

    cudaFuncSetAttribute(gemm_hmma, cudaFuncAttributeMaxDynamicSharedMemorySize, GSMEM);

    prep_kernel<<<(G4 * H + 255) / 256, 256>>>(W_ih, W_hh, b_ih, b_hh);
    conv_w_kernel<<<(G4 * KIN) / 256, 256>>>(W_ih);
    conv_f_kernel<<<(L * KIN) / 256, 256>>>(x, hi);
    gemm_hmma<<<dim3(KIN / 128, L / 128), 256, GSMEM>>>(nullptr);
    lstm_kernel<<<NBLK, NTHR>>>();
    fc_kernel<<<L / 8, 256>>>(W_fc, b_fc, out);
}

// round 17
// speedup vs baseline: 1.2572x; 1.2572x over previous
#include <cuda_runtime.h>
#include <cuda_fp16.h>
#include <cstdint>
#include <math.h>

#define H      1024
#define L      512
#define G4     4096
#define KIN    4096
#define FIVEH  5120
#define LABELS 122
#define NBLK   128
#define NTHR   512

// ---- static device scratch ----
__device__ float g_Wrec[G4 * H];                 // 16 MB
__device__ float g_bias[G4];
__device__ float g_P[L * G4];                    // 8 MB
__device__ float g_outs[L * H];                  // 2 MB
__device__ int   g_pub[2][NBLK][32];             // publish lines: 8 h-words + flag@[8], 128B each
__device__ __half g_W_h[G4 * KIN];               // 32 MB  (fp16 truncation of W_ih[:, :4096])
__device__ __half g_F_h[L * KIN];                // 4 MB   (fp16 truncation of feats)

// ============ PTX helpers (plain sm_80+ features only) ============
__device__ __forceinline__ uint32_t smem_u32(const void* p) {
    uint32_t a;
    asm("{ .reg .u64 t; cvta.to.shared.u64 t, %1; cvt.u32.u64 %0, t; }" : "=r"(a) : "l"(p));
    return a;
}
#define CP_ASYNC16(dst, src) \
    asm volatile("cp.async.cg.shared.global [%0], [%1], 16;" :: "r"(dst), "l"(src))
#define CP_COMMIT() asm volatile("cp.async.commit_group;" ::: "memory")
#define CP_WAIT(n)  asm volatile("cp.async.wait_group %0;" :: "n"(n) : "memory")

__device__ __forceinline__ void ldm_x4(uint32_t& d0, uint32_t& d1, uint32_t& d2, uint32_t& d3,
                                       uint32_t addr) {
    asm volatile("ldmatrix.sync.aligned.m8n8.x4.shared.b16 {%0,%1,%2,%3}, [%4];"
                 : "=r"(d0), "=r"(d1), "=r"(d2), "=r"(d3) : "r"(addr));
}
__device__ __forceinline__ void mma_f16(float* c, const uint32_t* a, const uint32_t* b) {
    asm volatile("mma.sync.aligned.m16n8k16.row.col.f32.f16.f16.f32 "
                 "{%0,%1,%2,%3}, {%4,%5,%6,%7}, {%8,%9}, {%0,%1,%2,%3};"
                 : "+f"(c[0]), "+f"(c[1]), "+f"(c[2]), "+f"(c[3])
                 : "r"(a[0]), "r"(a[1]), "r"(a[2]), "r"(a[3]), "r"(b[0]), "r"(b[1]));
}
__device__ __forceinline__ void fma2(float2& d, const float2& a, const float2& b) {
    unsigned long long dd = *reinterpret_cast<const unsigned long long*>(&d);
    unsigned long long aa = *reinterpret_cast<const unsigned long long*>(&a);
    unsigned long long bb = *reinterpret_cast<const unsigned long long*>(&b);
    asm("fma.rn.f32x2 %0, %1, %2, %0;" : "+l"(dd) : "l"(aa), "l"(bb));
    d = *reinterpret_cast<float2*>(&dd);
}
__device__ __forceinline__ float sigm_f(float x) {
    return __fdividef(1.f, 1.f + __expf(-x));
}
__device__ __forceinline__ float tanh_f(float x) {
    return __fdividef(2.f, 1.f + __expf(-2.f * x)) - 1.f;
}

// ============================================================
// Kernel 1a: W_rec = W_ih[:,4096:] + W_hh, bias, pub flags
// ============================================================
__global__ void prep_kernel(const float* __restrict__ W_ih, const float* __restrict__ W_hh,
                            const float* __restrict__ b_ih, const float* __restrict__ b_hh) {
    int idx = blockIdx.x * blockDim.x + threadIdx.x;
    if (idx < G4 * H) {
        int r = idx >> 10, j = idx & 1023;
        g_Wrec[idx] = W_ih[(size_t)r * FIVEH + KIN + j] + W_hh[idx];
    }
    if (idx < G4) g_bias[idx] = b_ih[idx] + b_hh[idx];
    if (idx < 2 * NBLK * 32) (&g_pub[0][0][0])[idx] = 0;
}

// Kernel 1b: W_ih[:, :4096] -> fp16
__global__ void conv_w_kernel(const float* __restrict__ W_ih) {
    int idx = blockIdx.x * blockDim.x + threadIdx.x;     // 16.7M
    int r = idx >> 12, c = idx & 4095;
    g_W_h[idx] = __float2half_rn(W_ih[(size_t)r * FIVEH + c]);
}

// Kernel 1c: feats = concat(x, hi) -> fp16
__global__ void conv_f_kernel(const float* __restrict__ x, const float* __restrict__ hi) {
    int idx = blockIdx.x * blockDim.x + threadIdx.x;     // 2M
    int r = idx >> 12, c = idx & 4095;
    float v = (c < 2048) ? x[(size_t)r * 2048 + c] : hi[(size_t)r * 2048 + (c - 2048)];
    g_F_h[idx] = __float2half_rn(v);
}

// ============================================================
// Kernel 2: fp16 HMMA GEMM, 1-product (F_h * W_h) — measured 81us.
// 4-stage cp.async pipeline; BM=BN=128, BK=32, grid 128.
// ============================================================
#define BK       32
#define KTILES   (KIN / BK)          // 128
#define LDS_B    80                  // padded row stride in bytes (40 fp16)
#define T_AH     0                   // 128 rows * 80B = 10240
#define T_BH     10240
#define STAGE_B  20480
#define NSTAGE   4
#define GSMEM    (NSTAGE * STAGE_B)  // 81920

__global__ __launch_bounds__(256, 1)
void gemm_hmma(float* __restrict__ dummy) {
    extern __shared__ char smem[];
    uint32_t sb = smem_u32(smem);
    int tid = threadIdx.x, lane = tid & 31, wid = tid >> 5;
    int warp_m = wid >> 2, warp_n = wid & 3;     // 2 x 4 warps
    int bn = blockIdx.x, bm = blockIdx.y;        // 32 x 4

    // ---- cp.async mapping: 1024 16B-chunks/stage = 4/thread ----
    const char* gsrc[4];
    uint32_t    sdst[4];
#pragma unroll
    for (int j = 0; j < 4; j++) {
        int c = j * 256 + tid;
        int tile = c >> 9, cc = c & 511, row = cc >> 2, seg = cc & 3;
        const __half* base = tile ? g_W_h : g_F_h;
        int grow = (tile ? bn : bm) * 128 + row;
        gsrc[j] = (const char*)(base + (size_t)grow * KIN + seg * 8);
        sdst[j] = sb + tile * 10240 + row * LDS_B + seg * 16;
    }

    int r8 = lane & 7, mi01 = (lane >> 3) & 1, kh = (lane >> 4) & 1;
    uint32_t aoff = (uint32_t)((warp_m * 64 + mi01 * 8 + r8) * LDS_B + kh * 16);
    uint32_t boff = (uint32_t)((warp_n * 32 + mi01 * 8 + r8) * LDS_B + kh * 16);

    float acc[4][4][4];
#pragma unroll
    for (int i = 0; i < 4; i++)
#pragma unroll
        for (int j = 0; j < 4; j++)
#pragma unroll
            for (int q = 0; q < 4; q++) acc[i][j][q] = 0.f;

    // prologue: stages 0..2
#pragma unroll
    for (int s = 0; s < NSTAGE - 1; s++) {
#pragma unroll
        for (int j = 0; j < 4; j++)
            CP_ASYNC16(sdst[j] + s * STAGE_B, gsrc[j] + (size_t)s * BK * 2);
        CP_COMMIT();
    }

    for (int kt = 0; kt < KTILES; kt++) {
        int kp = kt + NSTAGE - 1;
        if (kp < KTILES) {
            uint32_t stoff = (kp & (NSTAGE - 1)) * STAGE_B;
            size_t goff = (size_t)kp * BK * 2;
#pragma unroll
            for (int j = 0; j < 4; j++) CP_ASYNC16(sdst[j] + stoff, gsrc[j] + goff);
        }
        CP_COMMIT();                 // possibly empty — uniform group accounting
        CP_WAIT(NSTAGE - 1);
        __syncthreads();

        uint32_t st = sb + (kt & (NSTAGE - 1)) * STAGE_B;
#pragma unroll
        for (int ks = 0; ks < 2; ks++) {
            uint32_t ko = ks * 32;
            uint32_t ah[4][4], bh[4][2];
#pragma unroll
            for (int mt = 0; mt < 4; mt++) {
                uint32_t a = aoff + mt * (16 * LDS_B) + ko;
                ldm_x4(ah[mt][0], ah[mt][1], ah[mt][2], ah[mt][3], st + T_AH + a);
            }
#pragma unroll
            for (int g = 0; g < 2; g++) {
                uint32_t b = boff + g * (16 * LDS_B) + ko;
                uint32_t d0, d1, d2, d3;
                ldm_x4(d0, d1, d2, d3, st + T_BH + b);
                bh[g * 2][0] = d0; bh[g * 2][1] = d2;
                bh[g * 2 + 1][0] = d1; bh[g * 2 + 1][1] = d3;
            }
#pragma unroll
            for (int mt = 0; mt < 4; mt++)
#pragma unroll
                for (int nt = 0; nt < 4; nt++)
                    mma_f16(acc[mt][nt], ah[mt], bh[nt]);
        }
        __syncthreads();
    }

    int gid = lane >> 2, tig = lane & 3;
#pragma unroll
    for (int mt = 0; mt < 4; mt++) {
        int row0 = bm * 128 + warp_m * 64 + mt * 16 + gid;
#pragma unroll
        for (int nt = 0; nt < 4; nt++) {
            int col = bn * 128 + warp_n * 32 + nt * 8 + tig * 2;
            float2 bias2 = *(const float2*)&g_bias[col];
            float2 v0 = make_float2(acc[mt][nt][0] + bias2.x, acc[mt][nt][1] + bias2.y);
            float2 v1 = make_float2(acc[mt][nt][2] + bias2.x, acc[mt][nt][3] + bias2.y);
            *(float2*)&g_P[(size_t)row0 * G4 + col] = v0;
            *(float2*)&g_P[(size_t)(row0 + 8) * G4 + col] = v1;
        }
    }
    if (dummy) *dummy = 0.f;
}

// ============================================================
// Kernel 3: persistent LSTM recurrence — byte-exact R11 (best measured).
// Poll = relaxed spin (2 tight, then nanosleep 40) + acquire RE-LOAD
// (cheap L2 hit; NOT fence.acq_rel — measured +440us regression in R16).
// ============================================================
__global__ __launch_bounds__(NTHR, 1) void lstm_kernel() {
    __shared__ float h_sh[H];
    __shared__ float red[32][4];

    int tid = threadIdx.x, b = blockIdx.x;
    int w = tid >> 5, l = tid & 31;
    int rg = w >> 1;                  // row group 0..7 (4 rows each)
    int cc = w & 1;                   // col chunk 0..1 (512 cols each)
    int jbase = b * 8;

    float2 wreg[4][8];
#pragma unroll
    for (int row = 0; row < 4; row++) {
        int rr = rg * 4 + row;
        int r = (rr >> 3) * 1024 + jbase + (rr & 7);
        const float2* wp = (const float2*)(g_Wrec + (size_t)r * H) + cc * 256;
#pragma unroll
        for (int i = 0; i < 8; i++) wreg[row][i] = wp[i * 32 + l];
    }
    h_sh[tid] = 0.f; h_sh[tid + 512] = 0.f;
    float c_reg = 0.f;
    int prow = (l >> 3) * 1024 + jbase + (l & 7);   // used by warp 15
    float pval = 0.f, pval_next = 0.f;
    if (w == 15) pval = __ldcg(&g_P[prow]);
    __syncthreads();

    for (int t = 0; t < L; t++) {
        if (w == 15 && t + 1 < L) pval_next = __ldcg(&g_P[(size_t)(t + 1) * G4 + prow]);

        // ---- phase A: matvec slice (4 rows x 16 cols per thread) ----
        float2 acc[4];
#pragma unroll
        for (int row = 0; row < 4; row++) acc[row] = make_float2(0.f, 0.f);
        const float2* h2 = (const float2*)h_sh;
#pragma unroll
        for (int i = 0; i < 8; i++) {
            float2 hv = h2[cc * 256 + i * 32 + l];
#pragma unroll
            for (int row = 0; row < 4; row++) fma2(acc[row], wreg[row][i], hv);
        }
        float a0 = acc[0].x + acc[0].y, a1 = acc[1].x + acc[1].y;
        float a2 = acc[2].x + acc[2].y, a3 = acc[3].x + acc[3].y;
        a0 += __shfl_xor_sync(0xffffffffu, a0, 16);
        a1 += __shfl_xor_sync(0xffffffffu, a1, 16);
        a2 += __shfl_xor_sync(0xffffffffu, a2, 16);
        a3 += __shfl_xor_sync(0xffffffffu, a3, 16);
        float v0 = (l & 16) ? a2 : a0;
        float v1 = (l & 16) ? a3 : a1;
        v0 += __shfl_xor_sync(0xffffffffu, v0, 8);
        v1 += __shfl_xor_sync(0xffffffffu, v1, 8);
        float u = (l & 8) ? v1 : v0;
        u += __shfl_xor_sync(0xffffffffu, u, 4);
        u += __shfl_xor_sync(0xffffffffu, u, 2);
        u += __shfl_xor_sync(0xffffffffu, u, 1);
        if ((l & 7) == 0) red[rg * 4 + (l >> 3)][cc] = u;
        __syncthreads();                         // BAR1

        // ---- phase B: gates+publish (warp 15) | poll (warps 11-14) ----
        if (w == 15) {
            float gate = pval + red[l][0] + red[l][1];
            pval = pval_next;
            float fg = __shfl_sync(0xffffffffu, gate, l + 8);
            float gg = __shfl_sync(0xffffffffu, gate, l + 16);
            float og = __shfl_sync(0xffffffffu, gate, l + 24);
            if (l < 8) {
                float cn = sigm_f(fg) * c_reg + sigm_f(gate) * tanh_f(gg);
                float hn = sigm_f(og) * tanh_f(cn);
                c_reg = cn;
                h_sh[jbase + l] = hn;                              // own slice -> smem
                g_outs[(size_t)t * H + jbase + l] = hn;            // for FC
                if (t < L - 1) g_pub[t & 1][b][l] = __float_as_int(hn);
            }
            __syncwarp(0xffffffffu);
            if (l == 0 && t < L - 1) {
                asm volatile("st.release.gpu.global.s32 [%0], %1;"
                             :: "l"(&g_pub[t & 1][b][8]), "r"(t + 1) : "memory");
            }
        } else if (w >= 11 && t < L - 1) {
            int ptid = tid - 352;                 // 0..127
            if (ptid != b) {
                const int* line = &g_pub[t & 1][ptid][0];
                int v, tries = 0;
                for (;;) {
                    asm volatile("ld.relaxed.gpu.global.s32 %0, [%1];"
                                 : "=r"(v) : "l"(line + 8) : "memory");
                    if (v >= t + 1) break;
                    if (++tries > 2) asm volatile("nanosleep.u32 40;");
                }
                asm volatile("ld.acquire.gpu.global.s32 %0, [%1];"
                             : "=r"(v) : "l"(line + 8) : "memory");
                int d0, d1, d2, d3, d4, d5, d6, d7;
                asm volatile("ld.global.cg.v4.s32 {%0,%1,%2,%3}, [%4];"
                             : "=r"(d0), "=r"(d1), "=r"(d2), "=r"(d3) : "l"(line) : "memory");
                asm volatile("ld.global.cg.v4.s32 {%0,%1,%2,%3}, [%4];"
                             : "=r"(d4), "=r"(d5), "=r"(d6), "=r"(d7) : "l"(line + 4) : "memory");
                int hb = ptid * 8;
                h_sh[hb + 0] = __int_as_float(d0); h_sh[hb + 1] = __int_as_float(d1);
                h_sh[hb + 2] = __int_as_float(d2); h_sh[hb + 3] = __int_as_float(d3);
                h_sh[hb + 4] = __int_as_float(d4); h_sh[hb + 5] = __int_as_float(d5);
                h_sh[hb + 6] = __int_as_float(d6); h_sh[hb + 7] = __int_as_float(d7);
            }
        }
        __syncthreads();                         // BAR2
    }
}

// ============================================================
// Kernel 4: FC — 8 timesteps per block for W_fc reuse
// ============================================================
__global__ __launch_bounds__(256) void fc_kernel(const float* __restrict__ W_fc,
                                                 const float* __restrict__ b_fc,
                                                 float* __restrict__ out) {
    int t0 = blockIdx.x * 8;
    __shared__ float hsh[8][H];
    for (int i = threadIdx.x; i < 8 * H; i += 256)
        hsh[i >> 10][i & 1023] = g_outs[(size_t)t0 * H + i];
    __syncthreads();
    int w = threadIdx.x >> 5, l = threadIdx.x & 31;
    for (int lab = w; lab < LABELS; lab += 8) {
        const float* wr = W_fc + (size_t)lab * H;
        float wv[32];
#pragma unroll
        for (int i = 0; i < 32; i++) wv[i] = wr[l + 32 * i];
        float s[8];
#pragma unroll
        for (int tt = 0; tt < 8; tt++) s[tt] = 0.f;
#pragma unroll
        for (int i = 0; i < 32; i++)
#pragma unroll
            for (int tt = 0; tt < 8; tt++) s[tt] += wv[i] * hsh[tt][l + 32 * i];
#pragma unroll
        for (int off = 16; off; off >>= 1)
#pragma unroll
            for (int tt = 0; tt < 8; tt++) s[tt] += __shfl_xor_sync(0xffffffffu, s[tt], off);
        if (l == 0) {
#pragma unroll
            for (int tt = 0; tt < 8; tt++)
                out[(size_t)(t0 + tt) * LABELS + lab] = s[tt] + b_fc[lab];
        }
    }
}

// ============================================================
extern "C" void kernel_launch(void* const* d_in, const int* in_sizes, int n_in,
                              void* d_out, int out_size) {
    const float* x    = (const float*)d_in[0];
    const float* hi   = (const float*)d_in[1];
    const float* W_ih = (const float*)d_in[2];
    const float* W_hh = (const float*)d_in[3];
    const float* b_ih = (const float*)d_in[4];
    const float* b_hh = (const float*)d_in[5];
    const float* W_fc = (const float*)d_in[6];
    const float* b_fc = (const float*)d_in[7];
    float* out = (float*)d_out;

    cudaFuncSetAttribute(gemm_hmma, cudaFuncAttributeMaxDynamicSharedMemorySize, GSMEM);

    prep_kernel<<<(G4 * H + 255) / 256, 256>>>(W_ih, W_hh, b_ih, b_hh);
    conv_w_kernel<<<(G4 * KIN) / 256, 256>>>(W_ih);
    conv_f_kernel<<<(L * KIN) / 256, 256>>>(x, hi);
    gemm_hmma<<<dim3(KIN / 128, L / 128), 256, GSMEM>>>(nullptr);
    lstm_kernel<<<NBLK, NTHR>>>();
    fc_kernel<<<L / 8, 256>>>(W_fc, b_fc, out);
}